// round 2
// baseline (speedup 1.0000x reference)
#include <cuda_runtime.h>
#include <math.h>

#define BB 256
#define UU 4096
#define VV 80
#define HH 1024
#define KK 10

// Output layout (concatenated flattened, in reference return order):
//   w               : BB*VV      floats (offset 0)
//   new_kappa       : BB*KK      floats (offset BB*VV)
//   phi_termination : BB*(UU+1)  floats (offset BB*VV + BB*KK)

__global__ __launch_bounds__(256) void softwindow_kernel(
    const float* __restrict__ x,        // [BB,1,HH]
    const float* __restrict__ c,        // [BB,UU,VV]
    const float* __restrict__ kappa,    // [BB,KK]
    const float* __restrict__ W,        // [3*KK,HH]
    const float* __restrict__ bias,     // [3*KK]
    const int*   __restrict__ lens32,   // [BB] int32 OR int64 viewed as int32 pairs
    float* __restrict__ out)
{
    __shared__ float x_sh[HH];          // 4 KB
    __shared__ float phi_sh[UU];        // 16 KB
    __shared__ float lin_sh[3 * KK];
    __shared__ float alpha_sh[KK];
    __shared__ float beta_sh[KK];
    __shared__ float nk_sh[KK];
    __shared__ int   ucut_sh;
    __shared__ int   or_sh[8];          // per-warp ORs for dtype probe
    __shared__ int   is64_sh;

    const int b    = blockIdx.x;
    const int tid  = threadIdx.x;
    const int warp = tid >> 5;
    const int lane = tid & 31;

    // ---- dtype probe: int64 layout <=> all odd int32 words in [0,256) are zero ----
    {
        int v = 0;
        if (tid < 128) v = lens32[2 * tid + 1];
        #pragma unroll
        for (int o = 16; o; o >>= 1) v |= __shfl_xor_sync(0xffffffffu, v, o);
        if (lane == 0) or_sh[warp] = v;
    }

    // ---- Stage x[b,:] into shared ----
    const float* xb = x + (size_t)b * HH;
    for (int h = tid; h < HH; h += 256) x_sh[h] = xb[h];
    __syncthreads();

    if (tid == 0) {
        int v = 0;
        #pragma unroll
        for (int i = 0; i < 8; i++) v |= or_sh[i];
        is64_sh = (v == 0);
    }

    // ---- lin = x[b] @ W^T + bias : 30 dot products, warp per output ----
    for (int j = warp; j < 3 * KK; j += 8) {
        const float* Wr = W + (size_t)j * HH;
        float s = 0.f;
        #pragma unroll 4
        for (int h = lane; h < HH; h += 32) s = fmaf(x_sh[h], Wr[h], s);
        #pragma unroll
        for (int o = 16; o; o >>= 1) s += __shfl_xor_sync(0xffffffffu, s, o);
        if (lane == 0) lin_sh[j] = s + bias[j];
    }
    __syncthreads();

    // ---- alpha, beta, new_kappa; write new_kappa output ----
    if (tid < KK) {
        float a  = expf(lin_sh[tid]);
        float be = expf(lin_sh[KK + tid]);
        float nk = kappa[(size_t)b * KK + tid] + expf(lin_sh[2 * KK + tid] - 3.9f);
        alpha_sh[tid] = a;
        beta_sh[tid]  = be;
        nk_sh[tid]    = nk;
        out[(size_t)BB * VV + (size_t)b * KK + tid] = nk;
    }
    __syncthreads();

    // ---- per-b cutoff: beyond it every exponent < -105 => fp32 exp == 0 exactly ----
    if (tid == 0) {
        float um = 0.f;
        #pragma unroll
        for (int k = 0; k < KK; k++)
            um = fmaxf(um, nk_sh[k] + sqrtf(105.0f / beta_sh[k]));
        int uc = (int)um + 1;
        if (uc > UU) uc = UU;       // cap: correctness never depends on the cutoff
        if (uc < 0)  uc = 0;
        ucut_sh = uc;
    }
    __syncthreads();
    const int ucut = ucut_sh;

    // ---- phi_termination for u in [0, UU]; stage phi (u < UU) in smem ----
    float* phit = out + (size_t)BB * VV + (size_t)BB * KK + (size_t)b * (UU + 1);
    float a_r[KK], be_r[KK], nk_r[KK];
    #pragma unroll
    for (int k = 0; k < KK; k++) { a_r[k] = alpha_sh[k]; be_r[k] = beta_sh[k]; nk_r[k] = nk_sh[k]; }

    for (int u = tid; u <= UU; u += 256) {
        float val = 0.f;
        if (u <= ucut) {
            const float uf = (float)u;
            #pragma unroll
            for (int k = 0; k < KK; k++) {
                float d   = nk_r[k] - uf;
                float arg = -be_r[k] * d * d;
                val += a_r[k] * expf(arg);
            }
        }
        phit[u] = val;
        if (u < UU) phi_sh[u] = val;
    }
    __syncthreads();

    // ---- length read (dtype-robust) ----
    const int len = is64_sh ? lens32[2 * b] : lens32[b];

    // ---- w[b,v] = sum_{u < min(len, ucut+1)} phi[u] * c[b,u,v] ----
    int umax = ucut + 1;
    if (len < umax) umax = len;
    if (umax < 0)   umax = 0;
    if (umax > UU)  umax = UU;

    if (tid < VV) {
        float acc = 0.f;
        const float* cb = c + (size_t)b * UU * VV + tid;
        for (int u = 0; u < umax; u++)
            acc = fmaf(phi_sh[u], cb[(size_t)u * VV], acc);
        out[(size_t)b * VV + tid] = acc;
    }
}

extern "C" void kernel_launch(void* const* d_in, const int* in_sizes, int n_in,
                              void* d_out, int out_size) {
    const float* x     = (const float*)d_in[0];
    const float* c     = (const float*)d_in[1];
    const float* kappa = (const float*)d_in[2];
    const float* W     = (const float*)d_in[3];
    const float* bias  = (const float*)d_in[4];
    const int*   lens  = (const int*)d_in[5];
    float* out = (float*)d_out;

    softwindow_kernel<<<BB, 256>>>(x, c, kappa, W, bias, lens, out);
}

// round 4
// speedup vs baseline: 1.3760x; 1.3760x over previous
#include <cuda_runtime.h>
#include <math.h>

#define BB 256
#define UU 4096
#define VV 80
#define HH 1024
#define KK 10
#define NT 512          // threads per block
#define NGRP 6          // einsum u-groups (NGRP*VV = 480 <= NT)

// Output layout (concatenated flattened, reference return order):
//   w               : BB*VV      floats (offset 0)
//   new_kappa       : BB*KK      floats (offset BB*VV)
//   phi_termination : BB*(UU+1)  floats (offset BB*VV + BB*KK)

__global__ __launch_bounds__(NT) void softwindow_kernel(
    const float* __restrict__ x,        // [BB,1,HH]
    const float* __restrict__ c,        // [BB,UU,VV]
    const float* __restrict__ kappa,    // [BB,KK]
    const float* __restrict__ W,        // [3*KK,HH]
    const float* __restrict__ bias,     // [3*KK]
    const int*   __restrict__ lens32,   // [BB] int32 OR int64 viewed as int32 pairs
    float* __restrict__ out)
{
    __shared__ float x_sh[HH];              // 4 KB
    __shared__ float phi_sh[UU];            // 16 KB
    __shared__ float lin_sh[3 * KK];
    __shared__ float alpha_sh[KK];
    __shared__ float beta_sh[KK];
    __shared__ float nk_sh[KK];
    __shared__ float part_sh[NGRP][VV];     // 1.9 KB einsum partials
    __shared__ int   ucut_sh;
    __shared__ int   or_sh[4];
    __shared__ int   is64_sh;

    const int b    = blockIdx.x;
    const int tid  = threadIdx.x;
    const int warp = tid >> 5;
    const int lane = tid & 31;

    // ---- dtype probe: int64 layout <=> all odd int32 words in [0,256) are zero ----
    if (tid < 128) {
        int v = lens32[2 * tid + 1];
        #pragma unroll
        for (int o = 16; o; o >>= 1) v |= __shfl_xor_sync(0xffffffffu, v, o);
        if (lane == 0) or_sh[warp] = v;
    }

    // ---- Stage x[b,:] into shared (float4, 256 threads) ----
    if (tid < HH / 4) {
        float4 v4 = ((const float4*)(x + (size_t)b * HH))[tid];
        ((float4*)x_sh)[tid] = v4;
    }
    __syncthreads();

    if (tid == 0) {
        int v = or_sh[0] | or_sh[1] | or_sh[2] | or_sh[3];
        is64_sh = (v == 0);
    }

    // ---- lin = x[b] @ W^T + bias : 30 dots, one warp per dot (16 warps, <=2 each) ----
    for (int j = warp; j < 3 * KK; j += 16) {
        const float4* Wr = (const float4*)(W + (size_t)j * HH);
        const float4* xs = (const float4*)x_sh;
        float s0 = 0.f, s1 = 0.f, s2 = 0.f, s3 = 0.f;
        #pragma unroll
        for (int i = 0; i < HH / 4 / 32; i++) {        // 8 iterations
            float4 wv = Wr[i * 32 + lane];
            float4 xv = xs[i * 32 + lane];
            s0 = fmaf(xv.x, wv.x, s0);
            s1 = fmaf(xv.y, wv.y, s1);
            s2 = fmaf(xv.z, wv.z, s2);
            s3 = fmaf(xv.w, wv.w, s3);
        }
        float s = (s0 + s1) + (s2 + s3);
        #pragma unroll
        for (int o = 16; o; o >>= 1) s += __shfl_xor_sync(0xffffffffu, s, o);
        if (lane == 0) lin_sh[j] = s + bias[j];
    }
    __syncthreads();

    // ---- alpha, beta, new_kappa; write new_kappa ----
    if (tid < KK) {
        float a  = expf(lin_sh[tid]);
        float be = expf(lin_sh[KK + tid]);
        float nk = kappa[(size_t)b * KK + tid] + expf(lin_sh[2 * KK + tid] - 3.9f);
        alpha_sh[tid] = a;
        beta_sh[tid]  = be;
        nk_sh[tid]    = nk;
        out[(size_t)BB * VV + (size_t)b * KK + tid] = nk;
    }
    __syncthreads();

    // ---- cutoff: beyond it every exponent < -105 => fp32 exp == 0 exactly ----
    if (tid == 0) {
        float um = 0.f;
        #pragma unroll
        for (int k = 0; k < KK; k++)
            um = fmaxf(um, nk_sh[k] + sqrtf(105.0f / beta_sh[k]));
        int uc = (int)um + 1;
        if (uc > UU) uc = UU;       // cap: correctness never depends on the cutoff
        if (uc < 0)  uc = 0;
        ucut_sh = uc;
    }
    __syncthreads();
    const int ucut = ucut_sh;

    float* phit = out + (size_t)BB * VV + (size_t)BB * KK + (size_t)b * (UU + 1);

    // ---- active phi: u in [0, ucut] (typically ~50) ----
    {
        float a_r[KK], be_r[KK], nk_r[KK];
        #pragma unroll
        for (int k = 0; k < KK; k++) { a_r[k] = alpha_sh[k]; be_r[k] = beta_sh[k]; nk_r[k] = nk_sh[k]; }
        for (int u = tid; u <= ucut; u += NT) {
            const float uf = (float)u;
            float val = 0.f;
            #pragma unroll
            for (int k = 0; k < KK; k++) {
                float d   = nk_r[k] - uf;
                float arg = -be_r[k] * d * d;
                val += a_r[k] * expf(arg);
            }
            phit[u] = val;
            if (u < UU) phi_sh[u] = val;
        }
    }
    __syncthreads();

    // ---- einsum: w[b,v] = sum_u phi[u]*c[b,u,v], u-parallel over NGRP groups ----
    const int len = is64_sh ? lens32[2 * b] : lens32[b];
    int umax = ucut + 1;
    if (len < umax) umax = len;
    if (umax < 0)   umax = 0;
    if (umax > UU)  umax = UU;

    if (tid < NGRP * VV) {
        const int v = tid % VV;
        const int g = tid / VV;
        float acc = 0.f;
        const float* cb = c + (size_t)b * UU * VV + v;
        for (int u = g; u < umax; u += NGRP)
            acc = fmaf(phi_sh[u], cb[(size_t)u * VV], acc);
        part_sh[g][v] = acc;
    }
    __syncthreads();
    if (tid < VV) {
        float acc = 0.f;
        #pragma unroll
        for (int g = 0; g < NGRP; g++) acc += part_sh[g][tid];
        out[(size_t)b * VV + tid] = acc;
    }

    // ---- zero tail of phi_termination: u in (ucut, UU] (pure stores, last) ----
    for (int u = ucut + 1 + tid; u <= UU; u += NT)
        phit[u] = 0.f;
}

extern "C" void kernel_launch(void* const* d_in, const int* in_sizes, int n_in,
                              void* d_out, int out_size) {
    const float* x     = (const float*)d_in[0];
    const float* c     = (const float*)d_in[1];
    const float* kappa = (const float*)d_in[2];
    const float* W     = (const float*)d_in[3];
    const float* bias  = (const float*)d_in[4];
    const int*   lens  = (const int*)d_in[5];
    float* out = (float*)d_out;

    softwindow_kernel<<<BB, NT>>>(x, c, kappa, W, bias, lens, out);
}

// round 5
// speedup vs baseline: 1.4558x; 1.0580x over previous
#include <cuda_runtime.h>
#include <math.h>

#define BB 256
#define UU 4096
#define VV 80
#define HH 1024
#define KK 10
#define NT 1024         // threads per block = 2 halves of 512
#define HT 512          // threads per half (one batch row each)
#define NGRP 6          // einsum u-groups (NGRP*VV = 480 <= HT)

// Output layout (concatenated flattened, reference return order):
//   w               : BB*VV      floats (offset 0)
//   new_kappa       : BB*KK      floats (offset BB*VV)
//   phi_termination : BB*(UU+1)  floats (offset BB*VV + BB*KK)

// per-half barrier: named barrier id s+1, 512 threads
#define HSYNC() asm volatile("bar.sync %0, %1;" :: "r"(s + 1), "r"(HT) : "memory")

__global__ __launch_bounds__(NT, 1) void softwindow_kernel(
    const float* __restrict__ x,        // [BB,1,HH]
    const float* __restrict__ c,        // [BB,UU,VV]
    const float* __restrict__ kappa,    // [BB,KK]
    const float* __restrict__ W,        // [3*KK,HH]
    const float* __restrict__ bias,     // [3*KK]
    const int*   __restrict__ lens32,   // [BB] int32 OR int64 viewed as int32 pairs
    float* __restrict__ out)
{
    __shared__ float x_sh[2][HH];            // 8 KB
    __shared__ float phi_sh[2][UU];          // 32 KB
    __shared__ float lin_sh[2][3 * KK];
    __shared__ float alpha_sh[2][KK];
    __shared__ float beta_sh[2][KK];
    __shared__ float nk_sh[2][KK];
    __shared__ float part_sh[2][NGRP][VV];   // 3.8 KB
    __shared__ int   ucut_sh[2];
    __shared__ int   or_sh[2][4];
    __shared__ int   is64_sh[2];

    const int tid_g = threadIdx.x;
    const int s     = tid_g >> 9;        // half id: 0 or 1
    const int tid   = tid_g & (HT - 1);  // local tid within half
    const int b     = 2 * blockIdx.x + s;
    const int warp  = tid >> 5;
    const int lane  = tid & 31;

    // ---- dtype probe: int64 layout <=> all odd int32 words in [0,256) are zero ----
    if (tid < 128) {
        int v = lens32[2 * tid + 1];
        #pragma unroll
        for (int o = 16; o; o >>= 1) v |= __shfl_xor_sync(0xffffffffu, v, o);
        if (lane == 0) or_sh[s][warp] = v;
    }

    // ---- stage x[b,:] into shared (float4, 256 threads of this half) ----
    if (tid < HH / 4) {
        float4 v4 = ((const float4*)(x + (size_t)b * HH))[tid];
        ((float4*)x_sh[s])[tid] = v4;
    }
    HSYNC();

    // ---- lin = x[b] @ W^T + bias : 30 dots, one warp per dot (16 warps, <=2 each) ----
    for (int j = warp; j < 3 * KK; j += 16) {
        const float4* Wr = (const float4*)(W + (size_t)j * HH);
        const float4* xs = (const float4*)x_sh[s];
        float s0 = 0.f, s1 = 0.f, s2 = 0.f, s3 = 0.f;
        #pragma unroll
        for (int i = 0; i < HH / 4 / 32; i++) {        // 8 iterations
            float4 wv = Wr[i * 32 + lane];
            float4 xv = xs[i * 32 + lane];
            s0 = fmaf(xv.x, wv.x, s0);
            s1 = fmaf(xv.y, wv.y, s1);
            s2 = fmaf(xv.z, wv.z, s2);
            s3 = fmaf(xv.w, wv.w, s3);
        }
        float sv = (s0 + s1) + (s2 + s3);
        #pragma unroll
        for (int o = 16; o; o >>= 1) sv += __shfl_xor_sync(0xffffffffu, sv, o);
        if (lane == 0) lin_sh[s][j] = sv + bias[j];
    }
    HSYNC();

    // ---- warp 0 of each half: alpha/beta/new_kappa + cutoff via warp max-reduce ----
    if (warp == 0) {
        float cut = 0.f;
        if (lane < KK) {
            float a  = expf(lin_sh[s][lane]);
            float be = expf(lin_sh[s][KK + lane]);
            float nk = kappa[(size_t)b * KK + lane] + expf(lin_sh[s][2 * KK + lane] - 3.9f);
            alpha_sh[s][lane] = a;
            beta_sh[s][lane]  = be;
            nk_sh[s][lane]    = nk;
            out[(size_t)BB * VV + (size_t)b * KK + lane] = nk;
            // beyond nk + sqrt(105/beta), every fp32 exp arg < -105 => exp == 0 exactly
            cut = nk + sqrtf(105.0f / be);
        }
        #pragma unroll
        for (int o = 16; o; o >>= 1) cut = fmaxf(cut, __shfl_xor_sync(0xffffffffu, cut, o));
        if (lane == 0) {
            int uc = (int)cut + 1;
            if (uc > UU) uc = UU;   // cap: correctness never depends on the cutoff
            if (uc < 0)  uc = 0;
            ucut_sh[s] = uc;
            is64_sh[s] = ((or_sh[s][0] | or_sh[s][1] | or_sh[s][2] | or_sh[s][3]) == 0);
        }
    }
    HSYNC();
    const int ucut = ucut_sh[s];

    float* phit = out + (size_t)BB * VV + (size_t)BB * KK + (size_t)b * (UU + 1);

    // ---- active phi: u in [0, ucut] (typically ~50) ----
    if (tid <= ucut) {
        float a_r[KK], be_r[KK], nk_r[KK];
        #pragma unroll
        for (int k = 0; k < KK; k++) {
            a_r[k] = alpha_sh[s][k]; be_r[k] = beta_sh[s][k]; nk_r[k] = nk_sh[s][k];
        }
        for (int u = tid; u <= ucut; u += HT) {
            const float uf = (float)u;
            float val = 0.f;
            #pragma unroll
            for (int k = 0; k < KK; k++) {
                float d   = nk_r[k] - uf;
                float arg = -be_r[k] * d * d;
                val += a_r[k] * expf(arg);
            }
            phit[u] = val;
            if (u < UU) phi_sh[s][u] = val;
        }
    }
    HSYNC();

    // ---- einsum: w[b,v] = sum_u phi[u]*c[b,u,v], u-parallel over NGRP groups ----
    const int len = is64_sh[s] ? lens32[2 * b] : lens32[b];
    int umax = ucut + 1;
    if (len < umax) umax = len;
    if (umax < 0)   umax = 0;
    if (umax > UU)  umax = UU;

    if (tid < NGRP * VV) {
        const int v = tid % VV;
        const int g = tid / VV;
        float acc = 0.f;
        const float* cb = c + (size_t)b * UU * VV + v;
        for (int u = g; u < umax; u += NGRP)
            acc = fmaf(phi_sh[s][u], cb[(size_t)u * VV], acc);
        part_sh[s][g][v] = acc;
    }
    HSYNC();
    if (tid < VV) {
        float acc = 0.f;
        #pragma unroll
        for (int g = 0; g < NGRP; g++) acc += part_sh[s][g][tid];
        out[(size_t)b * VV + tid] = acc;
    }

    // ---- zero tail of phi_termination: u in (ucut, UU] (pure stores, last) ----
    for (int u = ucut + 1 + tid; u <= UU; u += HT)
        phit[u] = 0.f;
}

extern "C" void kernel_launch(void* const* d_in, const int* in_sizes, int n_in,
                              void* d_out, int out_size) {
    const float* x     = (const float*)d_in[0];
    const float* c     = (const float*)d_in[1];
    const float* kappa = (const float*)d_in[2];
    const float* W     = (const float*)d_in[3];
    const float* bias  = (const float*)d_in[4];
    const int*   lens  = (const int*)d_in[5];
    float* out = (float*)d_out;

    softwindow_kernel<<<BB / 2, NT>>>(x, c, kappa, W, bias, lens, out);
}

// round 7
// speedup vs baseline: 1.6417x; 1.1277x over previous
#include <cuda_runtime.h>
#include <cuda_pipeline.h>
#include <math.h>

#define BB 256
#define UU 4096
#define VV 80
#define HH 1024
#define KK 10
#define NT 1024         // threads per block = 2 halves of 512
#define HT 512          // threads per half (one batch row each)
#define NGRP 6          // einsum u-groups (NGRP*VV = 480 <= HT)
#define UCAP 48         // prefetched c rows per b (covers typical ucut; fallback beyond)

// Output layout (concatenated flattened, reference return order):
//   w               : BB*VV      floats (offset 0)
//   new_kappa       : BB*KK      floats (offset BB*VV)
//   phi_termination : BB*(UU+1)  floats (offset BB*VV + BB*KK)

#define HSYNC() asm volatile("bar.sync %0, %1;" :: "r"(s + 1), "r"(HT) : "memory")

__global__ __launch_bounds__(NT, 1) void softwindow_kernel(
    const float* __restrict__ x,        // [BB,1,HH]
    const float* __restrict__ c,        // [BB,UU,VV]
    const float* __restrict__ kappa,    // [BB,KK]
    const float* __restrict__ W,        // [3*KK,HH]
    const float* __restrict__ bias,     // [3*KK]
    const int*   __restrict__ lens32,   // [BB] int32 OR int64 viewed as int32 pairs
    float* __restrict__ out)
{
    __shared__ float c_sh[2][UCAP * VV];     // 30 KB  (48 rows x 80 f32 per half)
    __shared__ float x_sh[2][HH];            // 8 KB
    __shared__ float phi_sh[2][UCAP];        // 384 B
    __shared__ float lin_sh[2][3 * KK];
    __shared__ float alpha_sh[2][KK];
    __shared__ float beta_sh[2][KK];
    __shared__ float nk_sh[2][KK];
    __shared__ float part_sh[2][NGRP][VV];   // 3.84 KB
    __shared__ int   ucut_sh[2];
    __shared__ int   or_sh[2][4];
    __shared__ int   is64_sh[2];

    const int tid_g = threadIdx.x;
    const int s     = tid_g >> 9;        // half id: 0 or 1
    const int tid   = tid_g & (HT - 1);  // local tid within half
    const int b     = 2 * blockIdx.x + s;
    const int warp  = tid >> 5;
    const int lane  = tid & 31;

    // ---- speculative prefetch: first UCAP rows of c[b] (contiguous 15 KB) ----
    {
        const float4* src = (const float4*)(c + (size_t)b * UU * VV);
        float4*       dst = (float4*)c_sh[s];
        for (int i = tid; i < UCAP * VV / 4; i += HT)      // 960 float4 per half
            __pipeline_memcpy_async(&dst[i], &src[i], 16);
        __pipeline_commit();
    }

    // ---- dtype probe: int64 layout <=> all odd int32 words in [0,256) are zero ----
    if (tid < 128) {
        int v = lens32[2 * tid + 1];
        #pragma unroll
        for (int o = 16; o; o >>= 1) v |= __shfl_xor_sync(0xffffffffu, v, o);
        if (lane == 0) or_sh[s][warp] = v;
    }

    // ---- stage x[b,:] into shared ----
    if (tid < HH / 4) {
        float4 v4 = ((const float4*)(x + (size_t)b * HH))[tid];
        ((float4*)x_sh[s])[tid] = v4;
    }
    HSYNC();

    // ---- lin = x[b] @ W^T + bias : 30 dots, one warp per dot ----
    for (int j = warp; j < 3 * KK; j += 16) {
        const float4* Wr = (const float4*)(W + (size_t)j * HH);
        const float4* xs = (const float4*)x_sh[s];
        float s0 = 0.f, s1 = 0.f, s2 = 0.f, s3 = 0.f;
        #pragma unroll
        for (int i = 0; i < HH / 4 / 32; i++) {        // 8 iterations
            float4 wv = Wr[i * 32 + lane];
            float4 xv = xs[i * 32 + lane];
            s0 = fmaf(xv.x, wv.x, s0);
            s1 = fmaf(xv.y, wv.y, s1);
            s2 = fmaf(xv.z, wv.z, s2);
            s3 = fmaf(xv.w, wv.w, s3);
        }
        float sv = (s0 + s1) + (s2 + s3);
        #pragma unroll
        for (int o = 16; o; o >>= 1) sv += __shfl_xor_sync(0xffffffffu, sv, o);
        if (lane == 0) lin_sh[s][j] = sv + bias[j];
    }
    HSYNC();

    // ---- warp 0: alpha/beta/new_kappa + cutoff via warp max-reduce ----
    if (warp == 0) {
        float cut = 0.f;
        if (lane < KK) {
            float a  = expf(lin_sh[s][lane]);
            float be = expf(lin_sh[s][KK + lane]);
            float nk = kappa[(size_t)b * KK + lane] + expf(lin_sh[s][2 * KK + lane] - 3.9f);
            alpha_sh[s][lane] = a;
            beta_sh[s][lane]  = be;
            nk_sh[s][lane]    = nk;
            out[(size_t)BB * VV + (size_t)b * KK + lane] = nk;
            // beyond nk + sqrt(105/beta), every fp32 exp arg < -105 => exp == 0 exactly
            cut = nk + sqrtf(105.0f / be);
        }
        #pragma unroll
        for (int o = 16; o; o >>= 1) cut = fmaxf(cut, __shfl_xor_sync(0xffffffffu, cut, o));
        if (lane == 0) {
            int uc = (int)cut + 1;
            if (uc > UU) uc = UU;   // cap: correctness never depends on the cutoff
            if (uc < 0)  uc = 0;
            ucut_sh[s] = uc;
            is64_sh[s] = ((or_sh[s][0] | or_sh[s][1] | or_sh[s][2] | or_sh[s][3]) == 0);
        }
    }
    HSYNC();
    const int ucut = ucut_sh[s];

    float* phit = out + (size_t)BB * VV + (size_t)BB * KK + (size_t)b * (UU + 1);

    // ---- active phi: u in [0, ucut] (typically ~25) ----
    if (tid <= ucut) {
        float a_r[KK], be_r[KK], nk_r[KK];
        #pragma unroll
        for (int k = 0; k < KK; k++) {
            a_r[k] = alpha_sh[s][k]; be_r[k] = beta_sh[s][k]; nk_r[k] = nk_sh[s][k];
        }
        for (int u = tid; u <= ucut; u += HT) {
            const float uf = (float)u;
            float val = 0.f;
            #pragma unroll
            for (int k = 0; k < KK; k++) {
                float d   = nk_r[k] - uf;
                float arg = -be_r[k] * d * d;
                val += a_r[k] * expf(arg);
            }
            phit[u] = val;
            if (u < UCAP) phi_sh[s][u] = val;
        }
    }
    __pipeline_wait_prior(0);   // c prefetch done (latency long since hidden)
    HSYNC();

    // ---- einsum: w[b,v] = sum_u phi[u]*c[b,u,v], u-parallel over NGRP groups ----
    const int len = is64_sh[s] ? lens32[2 * b] : lens32[b];
    int umax = ucut + 1;
    if (len < umax) umax = len;
    if (umax < 0)   umax = 0;
    if (umax > UU)  umax = UU;

    if (tid < NGRP * VV) {
        const int v = tid % VV;
        const int g = tid / VV;
        float acc = 0.f;
        // fast path: prefetched smem rows
        int ufast = umax < UCAP ? umax : UCAP;
        for (int u = g; u < ufast; u += NGRP)
            acc = fmaf(phi_sh[s][u], c_sh[s][u * VV + v], acc);
        if (umax > UCAP) {
            // rare fallback: gmem c + recomputed phi (no cross-phase gmem dependence)
            int u0 = g;
            while (u0 < UCAP) u0 += NGRP;
            const float* cb = c + (size_t)b * UU * VV + v;
            for (int u = u0; u < umax; u += NGRP) {
                const float uf = (float)u;
                float ph = 0.f;
                #pragma unroll
                for (int k = 0; k < KK; k++) {
                    float d = nk_sh[s][k] - uf;
                    ph += alpha_sh[s][k] * expf(-beta_sh[s][k] * d * d);
                }
                acc = fmaf(ph, cb[(size_t)u * VV], acc);
            }
        }
        part_sh[s][g][v] = acc;
    }
    HSYNC();
    if (tid < VV) {
        float acc = 0.f;
        #pragma unroll
        for (int g = 0; g < NGRP; g++) acc += part_sh[s][g][tid];
        out[(size_t)b * VV + tid] = acc;
    }

    // ---- zero tail of phi_termination: u in (ucut, UU] (pure stores, last) ----
    for (int u = ucut + 1 + tid; u <= UU; u += HT)
        phit[u] = 0.f;
}

extern "C" void kernel_launch(void* const* d_in, const int* in_sizes, int n_in,
                              void* d_out, int out_size) {
    const float* x     = (const float*)d_in[0];
    const float* c     = (const float*)d_in[1];
    const float* kappa = (const float*)d_in[2];
    const float* W     = (const float*)d_in[3];
    const float* bias  = (const float*)d_in[4];
    const int*   lens  = (const int*)d_in[5];
    float* out = (float*)d_out;

    softwindow_kernel<<<BB / 2, NT>>>(x, c, kappa, W, bias, lens, out);
}